// round 14
// baseline (speedup 1.0000x reference)
#include <cuda_runtime.h>
#include <cstdint>

#define N_NODES 100000
#define C1 128
#define C2 64
#define E_MAX 1600000
#define SCAN_BLK 1024
#define SCAN_NB ((N_NODES + SCAN_BLK - 1) / SCAN_BLK)   // 98

#define N_TILES ((N_NODES + 127) / 128)                 // 782
#define N_CHUNKS 4
#define CHUNK_TILES ((N_TILES + N_CHUNKS - 1) / N_CHUNKS)   // 196

// ---------------- scratch (static device globals; no allocation) ----------------
__device__ float g_h1 [(size_t)N_NODES * C1];   // (x@W1) * dinv[row]
__device__ float g_h1b[(size_t)N_NODES * C1];   // relu(gcn1) output
__device__ float g_h2 [(size_t)N_NODES * C2];   // (h1b@W2) * dinv[row]
__device__ float g_dinv[N_NODES];
__device__ int   g_deg [N_NODES];
__device__ int   g_row [N_NODES + 1];           // CSR row offsets (by dst)
__device__ int   g_csr [E_MAX];                 // src index per edge, grouped by dst
__device__ int   g_cursor[N_NODES];
__device__ int   g_bsum[SCAN_NB];
__device__ int   g_is64;

// ---------------- packed f32x2 helpers ----------------
#define PACK2(out, lo, hi) \
    asm("mov.b64 %0, {%1, %2};" : "=l"(out) : "f"(lo), "f"(hi))
#define UNPACK2(lo, hi, in) \
    asm("mov.b64 {%0, %1}, %2;" : "=f"(lo), "=f"(hi) : "l"(in))
#define FMA2(d, a, b, c) \
    asm("fma.rn.f32x2 %0, %1, %2, %3;" : "=l"(d) : "l"(a), "l"(b), "l"(c))

// ---------------- edge dtype detection (parallel) ----------------
// int64 values < 100000 => every high 32-bit word is 0.
// int32 => odd int32 positions are random node ids; P(all 1024 zero) ~ 0.
__global__ void detect_kernel(const int* __restrict__ ei) {
    __shared__ int s;
    if (threadIdx.x == 0) s = 0;
    __syncthreads();
    int any = 0;
    for (int i = threadIdx.x; i < 1024; i += blockDim.x) any |= ei[2 * i + 1];
    if (any) atomicOr(&s, 1);
    __syncthreads();
    if (threadIdx.x == 0) g_is64 = (s == 0) ? 1 : 0;
}

__device__ __forceinline__ int load_idx(const void* ei, long long pos) {
    if (g_is64) return (int)((const long long*)ei)[pos];
    return ((const int*)ei)[pos];
}

// ---------------- degree + dinv ----------------
__global__ void deg_kernel(const void* __restrict__ ei, int E) {
    int t = blockIdx.x * blockDim.x + threadIdx.x;
    if (t >= E) return;
    int d = load_idx(ei, (long long)E + t);
    atomicAdd(&g_deg[d], 1);
}

__global__ void dinv_kernel() {
    int t = blockIdx.x * blockDim.x + threadIdx.x;
    if (t < N_NODES) g_dinv[t] = rsqrtf((float)g_deg[t] + 1.0f);
}

// ---------------- prefix scan over deg -> g_row ----------------
__global__ void scan_block_kernel() {
    __shared__ int sm[SCAN_BLK];
    int tid = threadIdx.x;
    int i = blockIdx.x * SCAN_BLK + tid;
    int v = (i < N_NODES) ? g_deg[i] : 0;
    sm[tid] = v;
    __syncthreads();
    #pragma unroll
    for (int off = 1; off < SCAN_BLK; off <<= 1) {
        int t = (tid >= off) ? sm[tid - off] : 0;
        __syncthreads();
        sm[tid] += t;
        __syncthreads();
    }
    if (i < N_NODES) g_row[i] = sm[tid] - v;        // exclusive
    if (tid == SCAN_BLK - 1) g_bsum[blockIdx.x] = sm[tid];
}

__global__ void scan_top_kernel() {
    __shared__ int sm[128];
    int tid = threadIdx.x;
    int v = (tid < SCAN_NB) ? g_bsum[tid] : 0;
    sm[tid] = v;
    __syncthreads();
    #pragma unroll
    for (int off = 1; off < 128; off <<= 1) {
        int t = (tid >= off) ? sm[tid - off] : 0;
        __syncthreads();
        sm[tid] += t;
        __syncthreads();
    }
    if (tid < SCAN_NB) g_bsum[tid] = sm[tid] - v;   // exclusive block offsets
    if (tid == 127) g_row[N_NODES] = sm[127];       // = E
}

__global__ void scan_add_kernel() {
    int i = blockIdx.x * blockDim.x + threadIdx.x;
    if (i < N_NODES) g_row[i] += g_bsum[i >> 10];
}

// ---------------- CSR fill ----------------
__global__ void fill_kernel(const void* __restrict__ ei, int E) {
    int t = blockIdx.x * blockDim.x + threadIdx.x;
    if (t >= E) return;
    int s = load_idx(ei, t);
    int d = load_idx(ei, (long long)E + t);
    int pos = g_row[d] + atomicAdd(&g_cursor[d], 1);
    g_csr[pos] = s;
}

// ---------------- SIMT SGEMM: packed f32x2 FMA + smem double buffering ----------------
// C[M,N] = (A[M,K] * B[K,N]) * dinv[row]   (row scaling fused into epilogue)
template <int BM, int BN, int BK, int TM, int TN>
__global__ void sgemm_scaled(int M, int N, int K,
                             const float* __restrict__ A,
                             const float* __restrict__ B,
                             const float* __restrict__ dinv,
                             float* __restrict__ C) {
    constexpr int numThreads = (BM / TM) * (BN / TN);
    constexpr int nA = (BM * BK) / (numThreads * 4);   // float4 A loads per thread
    constexpr int nB = (BK * BN) / (numThreads * 4);   // float4 B loads per thread
    const int cRow = blockIdx.y;
    const int cCol = blockIdx.x;

    __shared__ float As[2][BK][BM];   // transposed A tiles
    __shared__ float Bs[2][BK][BN];

    const int threadCol = threadIdx.x % (BN / TN);
    const int threadRow = threadIdx.x / (BN / TN);

    A += (size_t)cRow * BM * K;
    B += cCol * BN;
    C += (size_t)cRow * BM * N + cCol * BN;
    const int rowBase = cRow * BM;

    const int innerRowA = threadIdx.x / (BK / 4);
    const int innerColA = threadIdx.x % (BK / 4);
    constexpr int strideA = numThreads / (BK / 4);
    const int innerRowB = threadIdx.x / (BN / 4);
    const int innerColB = threadIdx.x % (BN / 4);

    bool rowOk[nA];
    #pragma unroll
    for (int i = 0; i < nA; i++)
        rowOk[i] = (rowBase + innerRowA + i * strideA) < M;

    unsigned long long accp[TM][TN / 2];
    #pragma unroll
    for (int i = 0; i < TM; i++)
        #pragma unroll
        for (int j = 0; j < TN / 2; j++) accp[i][j] = 0ULL;

    // prologue: load tile 0 into buffer 0
    {
        #pragma unroll
        for (int i = 0; i < nA; i++) {
            int r = innerRowA + i * strideA;
            float4 t = make_float4(0.f, 0.f, 0.f, 0.f);
            if (rowOk[i]) t = *(const float4*)(A + (size_t)r * K + innerColA * 4);
            As[0][innerColA * 4 + 0][r] = t.x;
            As[0][innerColA * 4 + 1][r] = t.y;
            As[0][innerColA * 4 + 2][r] = t.z;
            As[0][innerColA * 4 + 3][r] = t.w;
        }
        #pragma unroll
        for (int i = 0; i < nB; i++) {
            float4 t = *(const float4*)(B + (size_t)innerRowB * N + innerColB * 4);
            *(float4*)(&Bs[0][innerRowB][innerColB * 4]) = t;
        }
        A += BK;
        B += (size_t)BK * N;
    }
    __syncthreads();

    const int nSteps = K / BK;
    float4 pa[nA], pb[nB];
    for (int step = 0; step < nSteps; step++) {
        const int buf = step & 1;
        const bool hasNext = (step + 1) < nSteps;

        // issue global prefetch for next tile early (overlaps with compute)
        if (hasNext) {
            #pragma unroll
            for (int i = 0; i < nA; i++) {
                int r = innerRowA + i * strideA;
                pa[i] = make_float4(0.f, 0.f, 0.f, 0.f);
                if (rowOk[i]) pa[i] = *(const float4*)(A + (size_t)r * K + innerColA * 4);
            }
            #pragma unroll
            for (int i = 0; i < nB; i++)
                pb[i] = *(const float4*)(B + (size_t)innerRowB * N + innerColB * 4);
            A += BK;
            B += (size_t)BK * N;
        }

        #pragma unroll
        for (int k = 0; k < BK; k++) {
            float4 m0 = *(const float4*)(&As[buf][k][threadRow * TM]);
            float4 m1 = *(const float4*)(&As[buf][k][threadRow * TM + 4]);
            float4 n0 = *(const float4*)(&Bs[buf][k][threadCol * TN]);
            float4 n1 = *(const float4*)(&Bs[buf][k][threadCol * TN + 4]);
            unsigned long long np[4];
            PACK2(np[0], n0.x, n0.y);
            PACK2(np[1], n0.z, n0.w);
            PACK2(np[2], n1.x, n1.y);
            PACK2(np[3], n1.z, n1.w);
            float rm[TM] = {m0.x, m0.y, m0.z, m0.w, m1.x, m1.y, m1.z, m1.w};
            #pragma unroll
            for (int i = 0; i < TM; i++) {
                unsigned long long rm2;
                PACK2(rm2, rm[i], rm[i]);
                #pragma unroll
                for (int j = 0; j < TN / 2; j++)
                    FMA2(accp[i][j], rm2, np[j], accp[i][j]);
            }
        }

        if (hasNext) {
            const int nbuf = buf ^ 1;
            #pragma unroll
            for (int i = 0; i < nA; i++) {
                int r = innerRowA + i * strideA;
                As[nbuf][innerColA * 4 + 0][r] = pa[i].x;
                As[nbuf][innerColA * 4 + 1][r] = pa[i].y;
                As[nbuf][innerColA * 4 + 2][r] = pa[i].z;
                As[nbuf][innerColA * 4 + 3][r] = pa[i].w;
            }
            #pragma unroll
            for (int i = 0; i < nB; i++)
                *(float4*)(&Bs[nbuf][innerRowB][innerColB * 4]) = pb[i];
            __syncthreads();
        }
    }

    #pragma unroll
    for (int i = 0; i < TM; i++) {
        int r = threadRow * TM + i;
        if (rowBase + r >= M) continue;
        float s = __ldg(&dinv[rowBase + r]);
        float o[TN];
        #pragma unroll
        for (int j = 0; j < TN / 2; j++)
            UNPACK2(o[2 * j], o[2 * j + 1], accp[i][j]);
        #pragma unroll
        for (int j = 0; j < TN; j += 4) {
            float4 t;
            t.x = o[j + 0] * s; t.y = o[j + 1] * s;
            t.z = o[j + 2] * s; t.w = o[j + 3] * s;
            *(float4*)(&C[(size_t)r * N + threadCol * TN + j]) = t;
        }
    }
}

// ---------------- layer-1 aggregation (CSR, warp per node, fused epilogue) ----------------
// h is pre-scaled: h[v] = (x@W1)[v] * dinv[v].
// out[n] = relu( dinv[n] * (sum_{s->n} h[s] + h[n]) + b1 )
// Processes nodes [nodeStart, nodeStart + nodeCount).
__global__ void agg1_kernel(const float* __restrict__ h, const float* __restrict__ b1,
                            float* __restrict__ outp, int nodeStart, int nodeCount) {
    int warp = (int)(((long long)blockIdx.x * blockDim.x + threadIdx.x) >> 5);
    int lane = threadIdx.x & 31;
    if (warp >= nodeCount) return;
    int node = nodeStart + warp;
    int beg = __ldg(&g_row[node]);
    int end = __ldg(&g_row[node + 1]);
    const float4* h4 = (const float4*)h;

    float4 acc = __ldg(h4 + (size_t)node * (C1 / 4) + lane);   // self term (pre-scaled)
    int i = beg;
    for (; i + 4 <= end; i += 4) {
        int s0 = __ldg(&g_csr[i]);
        int s1 = __ldg(&g_csr[i + 1]);
        int s2 = __ldg(&g_csr[i + 2]);
        int s3 = __ldg(&g_csr[i + 3]);
        float4 v0 = __ldg(h4 + (size_t)s0 * (C1 / 4) + lane);
        float4 v1 = __ldg(h4 + (size_t)s1 * (C1 / 4) + lane);
        float4 v2 = __ldg(h4 + (size_t)s2 * (C1 / 4) + lane);
        float4 v3 = __ldg(h4 + (size_t)s3 * (C1 / 4) + lane);
        acc.x += (v0.x + v1.x) + (v2.x + v3.x);
        acc.y += (v0.y + v1.y) + (v2.y + v3.y);
        acc.z += (v0.z + v1.z) + (v2.z + v3.z);
        acc.w += (v0.w + v1.w) + (v2.w + v3.w);
    }
    for (; i < end; i++) {
        int s0 = __ldg(&g_csr[i]);
        float4 v0 = __ldg(h4 + (size_t)s0 * (C1 / 4) + lane);
        acc.x += v0.x; acc.y += v0.y; acc.z += v0.z; acc.w += v0.w;
    }

    float di = __ldg(&g_dinv[node]);
    float4 b = __ldg((const float4*)b1 + lane);
    float4 o;
    o.x = fmaxf(fmaf(di, acc.x, b.x), 0.f);
    o.y = fmaxf(fmaf(di, acc.y, b.y), 0.f);
    o.z = fmaxf(fmaf(di, acc.z, b.z), 0.f);
    o.w = fmaxf(fmaf(di, acc.w, b.w), 0.f);
    ((float4*)outp)[(size_t)node * (C1 / 4) + lane] = o;
}

// ---------------- layer-2 aggregation (CSR, half-warp per node, fused epilogue) ----------------
__global__ void agg2_kernel(const float* __restrict__ h, const float* __restrict__ b2,
                            float* __restrict__ outp) {
    int warp = (int)(((long long)blockIdx.x * blockDim.x + threadIdx.x) >> 5);
    int lane = threadIdx.x & 31;
    int node = warp * 2 + (lane >> 4);
    int sub  = lane & 15;
    if (node >= N_NODES) return;
    int beg = __ldg(&g_row[node]);
    int end = __ldg(&g_row[node + 1]);
    const float4* h4 = (const float4*)h;

    float4 acc = __ldg(h4 + (size_t)node * (C2 / 4) + sub);    // self term (pre-scaled)
    int i = beg;
    for (; i + 4 <= end; i += 4) {
        int s0 = __ldg(&g_csr[i]);
        int s1 = __ldg(&g_csr[i + 1]);
        int s2 = __ldg(&g_csr[i + 2]);
        int s3 = __ldg(&g_csr[i + 3]);
        float4 v0 = __ldg(h4 + (size_t)s0 * (C2 / 4) + sub);
        float4 v1 = __ldg(h4 + (size_t)s1 * (C2 / 4) + sub);
        float4 v2 = __ldg(h4 + (size_t)s2 * (C2 / 4) + sub);
        float4 v3 = __ldg(h4 + (size_t)s3 * (C2 / 4) + sub);
        acc.x += (v0.x + v1.x) + (v2.x + v3.x);
        acc.y += (v0.y + v1.y) + (v2.y + v3.y);
        acc.z += (v0.z + v1.z) + (v2.z + v3.z);
        acc.w += (v0.w + v1.w) + (v2.w + v3.w);
    }
    for (; i < end; i++) {
        int s0 = __ldg(&g_csr[i]);
        float4 v0 = __ldg(h4 + (size_t)s0 * (C2 / 4) + sub);
        acc.x += v0.x; acc.y += v0.y; acc.z += v0.z; acc.w += v0.w;
    }

    float di = __ldg(&g_dinv[node]);
    float4 b = __ldg((const float4*)b2 + sub);
    float4 o;
    o.x = fmaf(di, acc.x, b.x);
    o.y = fmaf(di, acc.y, b.y);
    o.z = fmaf(di, acc.z, b.z);
    o.w = fmaf(di, acc.w, b.w);
    ((float4*)outp)[(size_t)node * (C2 / 4) + sub] = o;
}

// ---------------- launch ----------------
extern "C" void kernel_launch(void* const* d_in, const int* in_sizes, int n_in,
                              void* d_out, int out_size) {
    const float* x  = (const float*)d_in[0];
    const float* W1 = (const float*)d_in[1];
    const float* b1 = (const float*)d_in[2];
    const float* W2 = (const float*)d_in[3];
    const float* b2 = (const float*)d_in[4];
    const void*  ei = d_in[5];
    const int E = in_sizes[5] / 2;
    float* out = (float*)d_out;

    // side stream + events, created once on the first (uncaptured) call
    static cudaStream_t s2 = nullptr;
    static cudaEvent_t evFork = nullptr, evJoin = nullptr, evG2 = nullptr;
    static cudaEvent_t evA[N_CHUNKS] = {nullptr, nullptr, nullptr, nullptr};
    if (s2 == nullptr) {
        cudaStreamCreateWithFlags(&s2, cudaStreamNonBlocking);
        cudaEventCreateWithFlags(&evFork, cudaEventDisableTiming);
        cudaEventCreateWithFlags(&evJoin, cudaEventDisableTiming);
        cudaEventCreateWithFlags(&evG2,   cudaEventDisableTiming);
        for (int c = 0; c < N_CHUNKS; c++)
            cudaEventCreateWithFlags(&evA[c], cudaEventDisableTiming);
    }

    void *p_h1, *p_h1b, *p_h2, *p_deg, *p_cur, *p_dinv;
    cudaGetSymbolAddress(&p_h1,   g_h1);
    cudaGetSymbolAddress(&p_h1b,  g_h1b);
    cudaGetSymbolAddress(&p_h2,   g_h2);
    cudaGetSymbolAddress(&p_deg,  g_deg);
    cudaGetSymbolAddress(&p_cur,  g_cursor);
    cudaGetSymbolAddress(&p_dinv, g_dinv);

    cudaMemsetAsync(p_deg, 0, sizeof(int) * N_NODES);
    cudaMemsetAsync(p_cur, 0, sizeof(int) * N_NODES);

    detect_kernel<<<1, 256>>>((const int*)ei);
    deg_kernel<<<(E + 255) / 256, 256>>>(ei, E);
    dinv_kernel<<<(N_NODES + 255) / 256, 256>>>();

    // fork: CSR build on side stream, concurrent with GEMM1 on the main stream
    cudaEventRecord(evFork, 0);
    cudaStreamWaitEvent(s2, evFork, 0);
    scan_block_kernel<<<SCAN_NB, SCAN_BLK, 0, s2>>>();
    scan_top_kernel<<<1, 128, 0, s2>>>();
    scan_add_kernel<<<(N_NODES + 255) / 256, 256, 0, s2>>>();
    fill_kernel<<<(E + 255) / 256, 256, 0, s2>>>(ei, E);
    cudaEventRecord(evJoin, s2);

    // GEMM1: h1 = (x @ W1) * dinv   [100000,128] x [128,128]
    {
        dim3 grid(1, N_TILES);
        sgemm_scaled<128, 128, 8, 8, 8><<<grid, 256>>>(
            N_NODES, C1, C1, x, W1, (const float*)p_dinv, (float*)p_h1);
    }

    // join: agg1 needs the CSR
    cudaStreamWaitEvent(0, evJoin, 0);

    // ---- chunk-pipelined agg1 (main stream) -> GEMM2 (side stream) ----
    // GEMM2 chunk c depends only on h1b rows of chunk c; agg2 waits for all GEMM2.
    for (int c = 0; c < N_CHUNKS; c++) {
        int tileStart = c * CHUNK_TILES;
        int tiles     = (tileStart + CHUNK_TILES <= N_TILES) ? CHUNK_TILES
                                                             : (N_TILES - tileStart);
        int nodeStart = tileStart * 128;
        int nodes     = (nodeStart + tiles * 128 <= N_NODES) ? tiles * 128
                                                             : (N_NODES - nodeStart);

        // agg1 chunk on main stream
        {
            long long threads = (long long)nodes * 32;
            int blocks = (int)((threads + 255) / 256);
            agg1_kernel<<<blocks, 256>>>((const float*)p_h1, b1, (float*)p_h1b,
                                         nodeStart, nodes);
        }
        cudaEventRecord(evA[c], 0);

        // GEMM2 chunk on side stream: h2[chunk] = (h1b[chunk] @ W2) * dinv[chunk]
        cudaStreamWaitEvent(s2, evA[c], 0);
        {
            dim3 grid(1, tiles);
            sgemm_scaled<128, 64, 8, 8, 8><<<grid, 128, 0, s2>>>(
                nodes, C2, C1,
                (const float*)p_h1b + (size_t)nodeStart * C1, W2,
                (const float*)p_dinv + nodeStart,
                (float*)p_h2 + (size_t)nodeStart * C2);
        }
    }
    cudaEventRecord(evG2, s2);
    cudaStreamWaitEvent(0, evG2, 0);

    // layer-2 aggregation + epilogue (half-warp per node) -> final output
    {
        long long threads = (long long)((N_NODES + 1) / 2) * 32;
        int blocks = (int)((threads + 255) / 256);
        agg2_kernel<<<blocks, 256>>>((const float*)p_h2, b2, out);
    }
}

// round 15
// speedup vs baseline: 1.0793x; 1.0793x over previous
#include <cuda_runtime.h>
#include <cstdint>

#define N_NODES 100000
#define C1 128
#define C2 64
#define E_MAX 1600000
#define SCAN_BLK 1024
#define SCAN_NB ((N_NODES + SCAN_BLK - 1) / SCAN_BLK)   // 98
#define N_TILES ((N_NODES + 127) / 128)                 // 782

// ---------------- scratch (static device globals; no allocation) ----------------
__device__ float g_h1 [(size_t)N_NODES * C1];   // x@W1 (UNSCALED)
__device__ float g_h1b[(size_t)N_NODES * C1];   // relu(gcn1) output
__device__ float g_h2 [(size_t)N_NODES * C2];   // (h1b@W2) * dinv[row]
__device__ float g_dinv[N_NODES];
__device__ int   g_deg [N_NODES];
__device__ int   g_row [N_NODES + 1];           // CSR row offsets (by dst)
__device__ int   g_csr [E_MAX];                 // src index per edge, grouped by dst
__device__ int   g_cursor[N_NODES];
__device__ int   g_bsum[SCAN_NB];
__device__ int   g_is64;

// ---------------- packed f32x2 helpers ----------------
#define PACK2(out, lo, hi) \
    asm("mov.b64 %0, {%1, %2};" : "=l"(out) : "f"(lo), "f"(hi))
#define UNPACK2(lo, hi, in) \
    asm("mov.b64 {%0, %1}, %2;" : "=f"(lo), "=f"(hi) : "l"(in))
#define FMA2(d, a, b, c) \
    asm("fma.rn.f32x2 %0, %1, %2, %3;" : "=l"(d) : "l"(a), "l"(b), "l"(c))

// ---------------- edge dtype detection (parallel) ----------------
// int64 values < 100000 => every high 32-bit word is 0.
// int32 => odd int32 positions are random node ids; P(all 1024 zero) ~ 0.
__global__ void detect_kernel(const int* __restrict__ ei) {
    __shared__ int s;
    if (threadIdx.x == 0) s = 0;
    __syncthreads();
    int any = 0;
    for (int i = threadIdx.x; i < 1024; i += blockDim.x) any |= ei[2 * i + 1];
    if (any) atomicOr(&s, 1);
    __syncthreads();
    if (threadIdx.x == 0) g_is64 = (s == 0) ? 1 : 0;
}

__device__ __forceinline__ int load_idx(const void* ei, long long pos) {
    if (g_is64) return (int)((const long long*)ei)[pos];
    return ((const int*)ei)[pos];
}

// ---------------- degree + dinv ----------------
__global__ void deg_kernel(const void* __restrict__ ei, int E) {
    int t = blockIdx.x * blockDim.x + threadIdx.x;
    if (t >= E) return;
    int d = load_idx(ei, (long long)E + t);
    atomicAdd(&g_deg[d], 1);
}

__global__ void dinv_kernel() {
    int t = blockIdx.x * blockDim.x + threadIdx.x;
    if (t < N_NODES) g_dinv[t] = rsqrtf((float)g_deg[t] + 1.0f);
}

// ---------------- prefix scan over deg -> g_row ----------------
__global__ void scan_block_kernel() {
    __shared__ int sm[SCAN_BLK];
    int tid = threadIdx.x;
    int i = blockIdx.x * SCAN_BLK + tid;
    int v = (i < N_NODES) ? g_deg[i] : 0;
    sm[tid] = v;
    __syncthreads();
    #pragma unroll
    for (int off = 1; off < SCAN_BLK; off <<= 1) {
        int t = (tid >= off) ? sm[tid - off] : 0;
        __syncthreads();
        sm[tid] += t;
        __syncthreads();
    }
    if (i < N_NODES) g_row[i] = sm[tid] - v;        // exclusive
    if (tid == SCAN_BLK - 1) g_bsum[blockIdx.x] = sm[tid];
}

__global__ void scan_top_kernel() {
    __shared__ int sm[128];
    int tid = threadIdx.x;
    int v = (tid < SCAN_NB) ? g_bsum[tid] : 0;
    sm[tid] = v;
    __syncthreads();
    #pragma unroll
    for (int off = 1; off < 128; off <<= 1) {
        int t = (tid >= off) ? sm[tid - off] : 0;
        __syncthreads();
        sm[tid] += t;
        __syncthreads();
    }
    if (tid < SCAN_NB) g_bsum[tid] = sm[tid] - v;   // exclusive block offsets
    if (tid == 127) g_row[N_NODES] = sm[127];       // = E
}

__global__ void scan_add_kernel() {
    int i = blockIdx.x * blockDim.x + threadIdx.x;
    if (i < N_NODES) g_row[i] += g_bsum[i >> 10];
}

// ---------------- CSR fill ----------------
__global__ void fill_kernel(const void* __restrict__ ei, int E) {
    int t = blockIdx.x * blockDim.x + threadIdx.x;
    if (t >= E) return;
    int s = load_idx(ei, t);
    int d = load_idx(ei, (long long)E + t);
    int pos = g_row[d] + atomicAdd(&g_cursor[d], 1);
    g_csr[pos] = s;
}

// ---------------- SIMT SGEMM: packed f32x2 FMA + smem double buffering ----------------
// C[M,N] = (A[M,K] * B[K,N]) [* dinv[row] if SCALE]
template <int BM, int BN, int BK, int TM, int TN, bool SCALE>
__global__ void sgemm_ffma2(int M, int N, int K,
                            const float* __restrict__ A,
                            const float* __restrict__ B,
                            const float* __restrict__ dinv,
                            float* __restrict__ C) {
    constexpr int numThreads = (BM / TM) * (BN / TN);
    constexpr int nA = (BM * BK) / (numThreads * 4);   // float4 A loads per thread
    constexpr int nB = (BK * BN) / (numThreads * 4);   // float4 B loads per thread
    const int cRow = blockIdx.y;
    const int cCol = blockIdx.x;

    __shared__ float As[2][BK][BM];   // transposed A tiles
    __shared__ float Bs[2][BK][BN];

    const int threadCol = threadIdx.x % (BN / TN);
    const int threadRow = threadIdx.x / (BN / TN);

    A += (size_t)cRow * BM * K;
    B += cCol * BN;
    C += (size_t)cRow * BM * N + cCol * BN;
    const int rowBase = cRow * BM;

    const int innerRowA = threadIdx.x / (BK / 4);
    const int innerColA = threadIdx.x % (BK / 4);
    constexpr int strideA = numThreads / (BK / 4);
    const int innerRowB = threadIdx.x / (BN / 4);
    const int innerColB = threadIdx.x % (BN / 4);

    bool rowOk[nA];
    #pragma unroll
    for (int i = 0; i < nA; i++)
        rowOk[i] = (rowBase + innerRowA + i * strideA) < M;

    unsigned long long accp[TM][TN / 2];
    #pragma unroll
    for (int i = 0; i < TM; i++)
        #pragma unroll
        for (int j = 0; j < TN / 2; j++) accp[i][j] = 0ULL;

    // prologue: load tile 0 into buffer 0
    {
        #pragma unroll
        for (int i = 0; i < nA; i++) {
            int r = innerRowA + i * strideA;
            float4 t = make_float4(0.f, 0.f, 0.f, 0.f);
            if (rowOk[i]) t = *(const float4*)(A + (size_t)r * K + innerColA * 4);
            As[0][innerColA * 4 + 0][r] = t.x;
            As[0][innerColA * 4 + 1][r] = t.y;
            As[0][innerColA * 4 + 2][r] = t.z;
            As[0][innerColA * 4 + 3][r] = t.w;
        }
        #pragma unroll
        for (int i = 0; i < nB; i++) {
            float4 t = *(const float4*)(B + (size_t)innerRowB * N + innerColB * 4);
            *(float4*)(&Bs[0][innerRowB][innerColB * 4]) = t;
        }
        A += BK;
        B += (size_t)BK * N;
    }
    __syncthreads();

    const int nSteps = K / BK;
    float4 pa[nA], pb[nB];
    for (int step = 0; step < nSteps; step++) {
        const int buf = step & 1;
        const bool hasNext = (step + 1) < nSteps;

        if (hasNext) {
            #pragma unroll
            for (int i = 0; i < nA; i++) {
                int r = innerRowA + i * strideA;
                pa[i] = make_float4(0.f, 0.f, 0.f, 0.f);
                if (rowOk[i]) pa[i] = *(const float4*)(A + (size_t)r * K + innerColA * 4);
            }
            #pragma unroll
            for (int i = 0; i < nB; i++)
                pb[i] = *(const float4*)(B + (size_t)innerRowB * N + innerColB * 4);
            A += BK;
            B += (size_t)BK * N;
        }

        #pragma unroll
        for (int k = 0; k < BK; k++) {
            float4 m0 = *(const float4*)(&As[buf][k][threadRow * TM]);
            float4 m1 = *(const float4*)(&As[buf][k][threadRow * TM + 4]);
            float4 n0 = *(const float4*)(&Bs[buf][k][threadCol * TN]);
            float4 n1 = *(const float4*)(&Bs[buf][k][threadCol * TN + 4]);
            unsigned long long np[4];
            PACK2(np[0], n0.x, n0.y);
            PACK2(np[1], n0.z, n0.w);
            PACK2(np[2], n1.x, n1.y);
            PACK2(np[3], n1.z, n1.w);
            float rm[TM] = {m0.x, m0.y, m0.z, m0.w, m1.x, m1.y, m1.z, m1.w};
            #pragma unroll
            for (int i = 0; i < TM; i++) {
                unsigned long long rm2;
                PACK2(rm2, rm[i], rm[i]);
                #pragma unroll
                for (int j = 0; j < TN / 2; j++)
                    FMA2(accp[i][j], rm2, np[j], accp[i][j]);
            }
        }

        if (hasNext) {
            const int nbuf = buf ^ 1;
            #pragma unroll
            for (int i = 0; i < nA; i++) {
                int r = innerRowA + i * strideA;
                As[nbuf][innerColA * 4 + 0][r] = pa[i].x;
                As[nbuf][innerColA * 4 + 1][r] = pa[i].y;
                As[nbuf][innerColA * 4 + 2][r] = pa[i].z;
                As[nbuf][innerColA * 4 + 3][r] = pa[i].w;
            }
            #pragma unroll
            for (int i = 0; i < nB; i++)
                *(float4*)(&Bs[nbuf][innerRowB][innerColB * 4]) = pb[i];
            __syncthreads();
        }
    }

    #pragma unroll
    for (int i = 0; i < TM; i++) {
        int r = threadRow * TM + i;
        if (rowBase + r >= M) continue;
        float s = SCALE ? __ldg(&dinv[rowBase + r]) : 1.0f;
        float o[TN];
        #pragma unroll
        for (int j = 0; j < TN / 2; j++)
            UNPACK2(o[2 * j], o[2 * j + 1], accp[i][j]);
        #pragma unroll
        for (int j = 0; j < TN; j += 4) {
            float4 t;
            if (SCALE) {
                t.x = o[j + 0] * s; t.y = o[j + 1] * s;
                t.z = o[j + 2] * s; t.w = o[j + 3] * s;
            } else {
                t.x = o[j + 0]; t.y = o[j + 1];
                t.z = o[j + 2]; t.w = o[j + 3];
            }
            *(float4*)(&C[(size_t)r * N + threadCol * TN + j]) = t;
        }
    }
}

// ---------------- layer-1 aggregation (CSR, warp per node, fused epilogue) ----------------
// h is UNSCALED (x@W1). Per-edge dinv[s] gathered (warp-broadcast, L2-resident).
// out[n] = relu( dinv[n]*(sum_{s->n} h[s]*dinv[s]) + dinv[n]^2 * h[n] + b1 )
__global__ void agg1_kernel(const float* __restrict__ h, const float* __restrict__ b1,
                            float* __restrict__ outp) {
    int warp = (int)(((long long)blockIdx.x * blockDim.x + threadIdx.x) >> 5);
    int lane = threadIdx.x & 31;
    if (warp >= N_NODES) return;
    int beg = __ldg(&g_row[warp]);
    int end = __ldg(&g_row[warp + 1]);
    const float4* h4 = (const float4*)h;

    float4 acc = make_float4(0.f, 0.f, 0.f, 0.f);
    int i = beg;
    for (; i + 4 <= end; i += 4) {
        int s0 = __ldg(&g_csr[i]);
        int s1 = __ldg(&g_csr[i + 1]);
        int s2 = __ldg(&g_csr[i + 2]);
        int s3 = __ldg(&g_csr[i + 3]);
        float n0 = __ldg(&g_dinv[s0]);
        float n1 = __ldg(&g_dinv[s1]);
        float n2 = __ldg(&g_dinv[s2]);
        float n3 = __ldg(&g_dinv[s3]);
        float4 v0 = __ldg(h4 + (size_t)s0 * (C1 / 4) + lane);
        float4 v1 = __ldg(h4 + (size_t)s1 * (C1 / 4) + lane);
        float4 v2 = __ldg(h4 + (size_t)s2 * (C1 / 4) + lane);
        float4 v3 = __ldg(h4 + (size_t)s3 * (C1 / 4) + lane);
        acc.x = fmaf(v0.x, n0, acc.x); acc.y = fmaf(v0.y, n0, acc.y);
        acc.z = fmaf(v0.z, n0, acc.z); acc.w = fmaf(v0.w, n0, acc.w);
        acc.x = fmaf(v1.x, n1, acc.x); acc.y = fmaf(v1.y, n1, acc.y);
        acc.z = fmaf(v1.z, n1, acc.z); acc.w = fmaf(v1.w, n1, acc.w);
        acc.x = fmaf(v2.x, n2, acc.x); acc.y = fmaf(v2.y, n2, acc.y);
        acc.z = fmaf(v2.z, n2, acc.z); acc.w = fmaf(v2.w, n2, acc.w);
        acc.x = fmaf(v3.x, n3, acc.x); acc.y = fmaf(v3.y, n3, acc.y);
        acc.z = fmaf(v3.z, n3, acc.z); acc.w = fmaf(v3.w, n3, acc.w);
    }
    for (; i < end; i++) {
        int s0 = __ldg(&g_csr[i]);
        float n0 = __ldg(&g_dinv[s0]);
        float4 v0 = __ldg(h4 + (size_t)s0 * (C1 / 4) + lane);
        acc.x = fmaf(v0.x, n0, acc.x); acc.y = fmaf(v0.y, n0, acc.y);
        acc.z = fmaf(v0.z, n0, acc.z); acc.w = fmaf(v0.w, n0, acc.w);
    }

    float di  = __ldg(&g_dinv[warp]);
    float di2 = di * di;
    float4 hh = __ldg(h4 + (size_t)warp * (C1 / 4) + lane);
    float4 b  = __ldg((const float4*)b1 + lane);
    float4 o;
    o.x = fmaxf(fmaf(di, acc.x, fmaf(di2, hh.x, b.x)), 0.f);
    o.y = fmaxf(fmaf(di, acc.y, fmaf(di2, hh.y, b.y)), 0.f);
    o.z = fmaxf(fmaf(di, acc.z, fmaf(di2, hh.z, b.z)), 0.f);
    o.w = fmaxf(fmaf(di, acc.w, fmaf(di2, hh.w, b.w)), 0.f);
    ((float4*)outp)[(size_t)warp * (C1 / 4) + lane] = o;
}

// ---------------- layer-2 aggregation (CSR, half-warp per node, fused epilogue) ----------------
// h is pre-scaled by dinv[row] (GEMM2 epilogue).
__global__ void agg2_kernel(const float* __restrict__ h, const float* __restrict__ b2,
                            float* __restrict__ outp) {
    int warp = (int)(((long long)blockIdx.x * blockDim.x + threadIdx.x) >> 5);
    int lane = threadIdx.x & 31;
    int node = warp * 2 + (lane >> 4);
    int sub  = lane & 15;
    if (node >= N_NODES) return;
    int beg = __ldg(&g_row[node]);
    int end = __ldg(&g_row[node + 1]);
    const float4* h4 = (const float4*)h;

    float4 acc = __ldg(h4 + (size_t)node * (C2 / 4) + sub);    // self term (pre-scaled)
    int i = beg;
    for (; i + 4 <= end; i += 4) {
        int s0 = __ldg(&g_csr[i]);
        int s1 = __ldg(&g_csr[i + 1]);
        int s2 = __ldg(&g_csr[i + 2]);
        int s3 = __ldg(&g_csr[i + 3]);
        float4 v0 = __ldg(h4 + (size_t)s0 * (C2 / 4) + sub);
        float4 v1 = __ldg(h4 + (size_t)s1 * (C2 / 4) + sub);
        float4 v2 = __ldg(h4 + (size_t)s2 * (C2 / 4) + sub);
        float4 v3 = __ldg(h4 + (size_t)s3 * (C2 / 4) + sub);
        acc.x += (v0.x + v1.x) + (v2.x + v3.x);
        acc.y += (v0.y + v1.y) + (v2.y + v3.y);
        acc.z += (v0.z + v1.z) + (v2.z + v3.z);
        acc.w += (v0.w + v1.w) + (v2.w + v3.w);
    }
    for (; i < end; i++) {
        int s0 = __ldg(&g_csr[i]);
        float4 v0 = __ldg(h4 + (size_t)s0 * (C2 / 4) + sub);
        acc.x += v0.x; acc.y += v0.y; acc.z += v0.z; acc.w += v0.w;
    }

    float di = __ldg(&g_dinv[node]);
    float4 b = __ldg((const float4*)b2 + sub);
    float4 o;
    o.x = fmaf(di, acc.x, b.x);
    o.y = fmaf(di, acc.y, b.y);
    o.z = fmaf(di, acc.z, b.z);
    o.w = fmaf(di, acc.w, b.w);
    ((float4*)outp)[(size_t)node * (C2 / 4) + sub] = o;
}

// ---------------- launch ----------------
extern "C" void kernel_launch(void* const* d_in, const int* in_sizes, int n_in,
                              void* d_out, int out_size) {
    const float* x  = (const float*)d_in[0];
    const float* W1 = (const float*)d_in[1];
    const float* b1 = (const float*)d_in[2];
    const float* W2 = (const float*)d_in[3];
    const float* b2 = (const float*)d_in[4];
    const void*  ei = d_in[5];
    const int E = in_sizes[5] / 2;
    float* out = (float*)d_out;

    // side stream + events, created once on the first (uncaptured) call
    static cudaStream_t s2 = nullptr;
    static cudaEvent_t evFork = nullptr, evJoin = nullptr;
    if (s2 == nullptr) {
        cudaStreamCreateWithFlags(&s2, cudaStreamNonBlocking);
        cudaEventCreateWithFlags(&evFork, cudaEventDisableTiming);
        cudaEventCreateWithFlags(&evJoin, cudaEventDisableTiming);
    }

    void *p_h1, *p_h1b, *p_h2, *p_deg, *p_cur, *p_dinv;
    cudaGetSymbolAddress(&p_h1,   g_h1);
    cudaGetSymbolAddress(&p_h1b,  g_h1b);
    cudaGetSymbolAddress(&p_h2,   g_h2);
    cudaGetSymbolAddress(&p_deg,  g_deg);
    cudaGetSymbolAddress(&p_cur,  g_cursor);
    cudaGetSymbolAddress(&p_dinv, g_dinv);

    cudaMemsetAsync(p_deg, 0, sizeof(int) * N_NODES);
    cudaMemsetAsync(p_cur, 0, sizeof(int) * N_NODES);

    // detect is the only pre-pass GEMM1's schedule waits on
    detect_kernel<<<1, 256>>>((const int*)ei);

    // fork: ENTIRE graph pre-pass + CSR build on side stream, hidden under GEMM1
    cudaEventRecord(evFork, 0);
    cudaStreamWaitEvent(s2, evFork, 0);
    deg_kernel<<<(E + 255) / 256, 256, 0, s2>>>(ei, E);
    dinv_kernel<<<(N_NODES + 255) / 256, 256, 0, s2>>>();
    scan_block_kernel<<<SCAN_NB, SCAN_BLK, 0, s2>>>();
    scan_top_kernel<<<1, 128, 0, s2>>>();
    scan_add_kernel<<<(N_NODES + 255) / 256, 256, 0, s2>>>();
    fill_kernel<<<(E + 255) / 256, 256, 0, s2>>>(ei, E);
    cudaEventRecord(evJoin, s2);

    // GEMM1 (no graph dependency): h1 = x @ W1, unscaled
    {
        dim3 grid(1, N_TILES);
        sgemm_ffma2<128, 128, 8, 8, 8, false><<<grid, 256>>>(
            N_NODES, C1, C1, x, W1, nullptr, (float*)p_h1);
    }

    // join: agg1 needs CSR + dinv
    cudaStreamWaitEvent(0, evJoin, 0);

    // layer-1 aggregation + epilogue (warp per node, per-edge dinv[s])
    {
        long long threads = (long long)N_NODES * 32;
        int blocks = (int)((threads + 255) / 256);
        agg1_kernel<<<blocks, 256>>>((const float*)p_h1, b1, (float*)p_h1b);
    }

    // GEMM2: h2 = (h1b @ W2) * dinv
    {
        dim3 grid(1, N_TILES);
        sgemm_ffma2<128, 64, 8, 8, 8, true><<<grid, 128>>>(
            N_NODES, C2, C1, (const float*)p_h1b, W2, (const float*)p_dinv, (float*)p_h2);
    }

    // layer-2 aggregation + epilogue (half-warp per node) -> final output
    {
        long long threads = (long long)((N_NODES + 1) / 2) * 32;
        int blocks = (int)((threads + 255) / 256);
        agg2_kernel<<<blocks, 256>>>((const float*)p_h2, b2, out);
    }
}